// round 3
// baseline (speedup 1.0000x reference)
#include <cuda_runtime.h>
#include <math.h>

// Fused: pred = data @ W + b  (Linear 64->3)
//        pred_n = pred / max(||pred||, eps)
//        cos = <pred_n, lab> / (max(||pred_n||,eps) * max(||lab||,eps))
//        out = nan_to_zero(acos(cos) * 180/pi)
//
// Layout: 8 threads per row ("octet"). Each thread loads 2x float4 of the
// data row (fully coalesced: warp = 4 rows = 1KB contiguous), accumulates
// 3 partial dots against its 8 W rows (register-resident, L1-cached),
// octet-reduces via shfl.xor, leader does the fp32 epilogue.

#define EPS 1e-8f
#define RAD2DEG 57.2957795130823208768f  // 180/pi

__global__ __launch_bounds__(256, 8)
void net_kernel(const float* __restrict__ data,   // [N, 64]
                const float* __restrict__ lab,    // [N, 3]
                const float* __restrict__ W,      // [64, 3]
                const float* __restrict__ b,      // [3]
                float* __restrict__ out,          // [N]
                int N)
{
    const int tid   = blockIdx.x * blockDim.x + threadIdx.x;
    const int row   = tid >> 3;        // 8 threads per row
    const int sub   = tid & 7;         // which 8-float chunk of the row
    if (row >= N) return;

    // ---- load my 8 W rows (k = sub*8 .. sub*8+7), 3 cols each ----
    // W is [64,3] row-major; these 24 scalars are L1-resident after warm-up.
    const int kbase = sub << 3;
    float w0[8], w1[8], w2[8];
#pragma unroll
    for (int j = 0; j < 8; ++j) {
        const float* wr = W + (kbase + j) * 3;
        w0[j] = __ldg(wr + 0);
        w1[j] = __ldg(wr + 1);
        w2[j] = __ldg(wr + 2);
    }

    // ---- stream my 32 bytes x2 of the data row ----
    const float4* drow = reinterpret_cast<const float4*>(data + (size_t)row * 64) + (sub << 1);
    float4 v0 = __ldg(drow + 0);
    float4 v1 = __ldg(drow + 1);

    float a0 = 0.f, a1 = 0.f, a2 = 0.f;
    const float x[8] = { v0.x, v0.y, v0.z, v0.w, v1.x, v1.y, v1.z, v1.w };
#pragma unroll
    for (int j = 0; j < 8; ++j) {
        a0 = fmaf(x[j], w0[j], a0);
        a1 = fmaf(x[j], w1[j], a1);
        a2 = fmaf(x[j], w2[j], a2);
    }

    // ---- octet reduction (lanes grouped 8-aligned, xor 1/2/4 stays in group) ----
#pragma unroll
    for (int m = 4; m >= 1; m >>= 1) {
        a0 += __shfl_xor_sync(0xFFFFFFFFu, a0, m);
        a1 += __shfl_xor_sync(0xFFFFFFFFu, a1, m);
        a2 += __shfl_xor_sync(0xFFFFFFFFu, a2, m);
    }

    if (sub == 0) {
        // pred = dot + b
        float p0 = a0 + __ldg(b + 0);
        float p1 = a1 + __ldg(b + 1);
        float p2 = a2 + __ldg(b + 2);

        const float* lr = lab + (size_t)row * 3;
        float l0 = __ldg(lr + 0);
        float l1 = __ldg(lr + 1);
        float l2 = __ldg(lr + 2);

        // F.normalize(pred): pred / max(||pred||, eps)
        float pn2  = fmaf(p0, p0, fmaf(p1, p1, p2 * p2));
        float pnrm = sqrtf(pn2);
        float inv  = 1.0f / fmaxf(pnrm, EPS);

        // cosine_similarity(pred_n, lab)
        float dotraw = fmaf(p0, l0, fmaf(p1, l1, p2 * l2));
        float dot    = dotraw * inv;               // <pred_n, lab>
        float na     = fmaxf(pnrm * inv, EPS);     // ||pred_n|| clamped
        float ln2    = fmaf(l0, l0, fmaf(l1, l1, l2 * l2));
        float nb     = fmaxf(sqrtf(ln2), EPS);

        float cosv = dot / (na * nb);
        float loss = acosf(cosv) * RAD2DEG;        // NaN if |cos|>1 -> handled below
        if (isnan(loss)) loss = 0.0f;

        out[row] = loss;
    }
}

extern "C" void kernel_launch(void* const* d_in, const int* in_sizes, int n_in,
                              void* d_out, int out_size)
{
    const float* data = (const float*)d_in[0];  // [N, 64]
    const float* lab  = (const float*)d_in[1];  // [N, 3]
    const float* W    = (const float*)d_in[2];  // [64, 3]
    const float* b    = (const float*)d_in[3];  // [3]
    float* out        = (float*)d_out;          // [N]

    const int N = out_size;                     // rows
    const int threads = 256;                    // 32 rows per block
    const int rows_per_block = threads / 8;
    const int blocks = (N + rows_per_block - 1) / rows_per_block;

    net_kernel<<<blocks, threads>>>(data, lab, W, b, out, N);
}